// round 1
// baseline (speedup 1.0000x reference)
#include <cuda_runtime.h>
#include <cstdint>

// Channel-group winner-take-all, group size 4, NCHW fp32.
// x: [B, C, H, W] = [32, 512, 56, 56]. For each (b, cg, h, w) the group is the
// 4 consecutive channels {4cg..4cg+3}; keep elements equal to the group max,
// zero the rest.
//
// Thread mapping: one thread per (b, cg, float4-chunk-of-HW). The 4 channel
// planes are H*W=3136 floats apart; loads/stores are float4 and fully
// coalesced across the warp (consecutive threads -> consecutive 16B chunks).

#define GB  32
#define GC  512
#define GHW (56 * 56)          // 3136, divisible by 4
#define GRP 4
#define HW4 (GHW / 4)          // 784 float4 chunks per plane
#define NCG (GC / GRP)         // 128 channel groups
#define NTHREADS_TOTAL (GB * NCG * HW4)   // 3,211,264

__global__ __launch_bounds__(256) void cgm_wta_kernel(
    const float4* __restrict__ x, float4* __restrict__ out)
{
    int tid = blockIdx.x * blockDim.x + threadIdx.x;
    if (tid >= NTHREADS_TOTAL) return;

    // Decompose tid -> (b, cg, p)
    int p  = tid % HW4;
    int t2 = tid / HW4;
    int cg = t2 % NCG;
    int b  = t2 / NCG;

    // float4 index of channel (4*cg) plane, chunk p
    // element offset = b*C*HW + (4*cg)*HW + 4*p ; /4 for float4 units
    long base = (long)b * (GC * (GHW / 4)) + (long)(cg * GRP) * (GHW / 4) + p;
    const int plane4 = GHW / 4;   // float4 stride between channel planes

    float4 v0 = x[base];
    float4 v1 = x[base + plane4];
    float4 v2 = x[base + 2 * plane4];
    float4 v3 = x[base + 3 * plane4];

    float4 m;
    m.x = fmaxf(fmaxf(v0.x, v1.x), fmaxf(v2.x, v3.x));
    m.y = fmaxf(fmaxf(v0.y, v1.y), fmaxf(v2.y, v3.y));
    m.z = fmaxf(fmaxf(v0.z, v1.z), fmaxf(v2.z, v3.z));
    m.w = fmaxf(fmaxf(v0.w, v1.w), fmaxf(v2.w, v3.w));

    float4 o0, o1, o2, o3;
    o0.x = (v0.x == m.x) ? v0.x : 0.0f;
    o0.y = (v0.y == m.y) ? v0.y : 0.0f;
    o0.z = (v0.z == m.z) ? v0.z : 0.0f;
    o0.w = (v0.w == m.w) ? v0.w : 0.0f;

    o1.x = (v1.x == m.x) ? v1.x : 0.0f;
    o1.y = (v1.y == m.y) ? v1.y : 0.0f;
    o1.z = (v1.z == m.z) ? v1.z : 0.0f;
    o1.w = (v1.w == m.w) ? v1.w : 0.0f;

    o2.x = (v2.x == m.x) ? v2.x : 0.0f;
    o2.y = (v2.y == m.y) ? v2.y : 0.0f;
    o2.z = (v2.z == m.z) ? v2.z : 0.0f;
    o2.w = (v2.w == m.w) ? v2.w : 0.0f;

    o3.x = (v3.x == m.x) ? v3.x : 0.0f;
    o3.y = (v3.y == m.y) ? v3.y : 0.0f;
    o3.z = (v3.z == m.z) ? v3.z : 0.0f;
    o3.w = (v3.w == m.w) ? v3.w : 0.0f;

    out[base]              = o0;
    out[base + plane4]     = o1;
    out[base + 2 * plane4] = o2;
    out[base + 3 * plane4] = o3;
}

extern "C" void kernel_launch(void* const* d_in, const int* in_sizes, int n_in,
                              void* d_out, int out_size)
{
    const float4* x   = (const float4*)d_in[0];
    float4*       out = (float4*)d_out;

    const int threads = 256;
    const int blocks  = (NTHREADS_TOTAL + threads - 1) / threads;  // 12544
    cgm_wta_kernel<<<blocks, threads>>>(x, out);
}